// round 3
// baseline (speedup 1.0000x reference)
#include <cuda_runtime.h>

#define NN 50000
#define EE 600000
#define HD 128
#define CC 40
#define NEG 0.1f

// ---------------- scratch (static device globals; no allocation) ----------------
__device__ float g_bufA[(size_t)NN * HD];
__device__ float g_bufB[(size_t)NN * HD];
__device__ float g_agg[(size_t)NN * HD];
__device__ float g_inv[NN];
__device__ int   g_cnt[NN];
__device__ int   g_rowptr[NN + 1];
__device__ int   g_fill[NN];
__device__ int   g_col[EE];

__device__ __forceinline__ float* dev_buf(int id) {
    return (id == 0) ? g_bufA : g_bufB;
}

// ---------------- CSR build ----------------
__global__ void k_zero_cnt() {
    int i = blockIdx.x * blockDim.x + threadIdx.x;
    if (i < NN) g_cnt[i] = 0;
}

__global__ void k_deg(const int* __restrict__ dst) {
    int e = blockIdx.x * blockDim.x + threadIdx.x;
    if (e < EE) atomicAdd(&g_cnt[dst[e]], 1);
}

// single-block chunked inclusive scan -> exclusive rowptr
__global__ void k_scan() {
    __shared__ int s[1024];
    __shared__ int carry;
    if (threadIdx.x == 0) { carry = 0; g_rowptr[0] = 0; }
    __syncthreads();
    for (int base = 0; base < NN; base += 1024) {
        int i = base + (int)threadIdx.x;
        int v = (i < NN) ? g_cnt[i] : 0;
        s[threadIdx.x] = v;
        __syncthreads();
        for (int off = 1; off < 1024; off <<= 1) {
            int t = (threadIdx.x >= (unsigned)off) ? s[threadIdx.x - off] : 0;
            __syncthreads();
            s[threadIdx.x] += t;
            __syncthreads();
        }
        if (i < NN) g_rowptr[i + 1] = carry + s[threadIdx.x];
        __syncthreads();
        if (threadIdx.x == 0) carry += s[1023];
        __syncthreads();
    }
}

__global__ void k_prep() {
    int i = blockIdx.x * blockDim.x + threadIdx.x;
    if (i < NN) {
        int b = g_rowptr[i];
        int e = g_rowptr[i + 1];
        g_fill[i] = b;
        int d = e - b;
        g_inv[i] = 1.0f / (float)(d > 0 ? d : 1);
    }
}

__global__ void k_fill(const int* __restrict__ src, const int* __restrict__ dst) {
    int e = blockIdx.x * blockDim.x + threadIdx.x;
    if (e < EE) {
        int pos = atomicAdd(&g_fill[dst[e]], 1);
        g_col[pos] = src[e];
    }
}

// ---------------- mean aggregation: one warp per node, float4 lanes ----------------
__global__ void k_agg(const float* __restrict__ ext, int in_id) {
    int warp = (blockIdx.x * blockDim.x + threadIdx.x) >> 5;
    if (warp >= NN) return;
    int lane = threadIdx.x & 31;
    const float* in = (in_id < 0) ? ext : dev_buf(in_id);
    int beg = g_rowptr[warp];
    int end = g_rowptr[warp + 1];
    float4 acc = make_float4(0.f, 0.f, 0.f, 0.f);
    for (int e = beg; e < end; e++) {
        int srcn = g_col[e];
        float4 v = *(const float4*)(in + (size_t)srcn * HD + lane * 4);
        acc.x += v.x; acc.y += v.y; acc.z += v.z; acc.w += v.w;
    }
    float iv = g_inv[warp];
    acc.x *= iv; acc.y *= iv; acc.z *= iv; acc.w *= iv;
    *(float4*)(g_agg + (size_t)warp * HD + lane * 4) = acc;
}

// ---------------- fused GEMM: out = leakyrelu(agg@Wl + x@Wr + b), Nout=128 ----------------
// BM=64, BN=128, BK=16; 256 threads; each thread 4 rows x 8 cols; f32x2 packed FMA.
__global__ __launch_bounds__(256) void k_gemm128(
    const float* __restrict__ ext_a2, int a2_id,
    const float* __restrict__ Wl, const float* __restrict__ Wr,
    const float* __restrict__ bias, int out_id)
{
    __shared__ float sA1[16][64];
    __shared__ float sA2[16][64];
    __shared__ float sWl[16][128];
    __shared__ float sWr[16][128];

    const float* A1 = g_agg;
    const float* A2 = (a2_id < 0) ? ext_a2 : dev_buf(a2_id);
    float* Out = dev_buf(out_id);

    int m0 = blockIdx.x * 64;
    int tid = (int)threadIdx.x;
    int ty = tid >> 4;          // 0..15 : rows ty*4..+3
    int tx = tid & 15;          // 0..15 : cols tx*8..+7

    unsigned long long acc[4][4];
#pragma unroll
    for (int i = 0; i < 4; i++)
#pragma unroll
        for (int j = 0; j < 4; j++) acc[i][j] = 0ULL;

    int lr = tid >> 2;            // 0..63 A-load row
    int lk = (tid & 3) * 4;       // k offset within BK
    int gr = m0 + lr; if (gr >= NN) gr = NN - 1;
    int wk = tid >> 4;            // 0..15 W-load k
    int wn = (tid & 15) * 8;      // W-load n

    for (int k0 = 0; k0 < HD; k0 += 16) {
        float4 a1v = *(const float4*)(A1 + (size_t)gr * HD + k0 + lk);
        float4 a2v = *(const float4*)(A2 + (size_t)gr * HD + k0 + lk);
        sA1[lk + 0][lr] = a1v.x; sA1[lk + 1][lr] = a1v.y;
        sA1[lk + 2][lr] = a1v.z; sA1[lk + 3][lr] = a1v.w;
        sA2[lk + 0][lr] = a2v.x; sA2[lk + 1][lr] = a2v.y;
        sA2[lk + 2][lr] = a2v.z; sA2[lk + 3][lr] = a2v.w;
        *(float4*)&sWl[wk][wn]     = *(const float4*)(Wl + (size_t)(k0 + wk) * 128 + wn);
        *(float4*)&sWl[wk][wn + 4] = *(const float4*)(Wl + (size_t)(k0 + wk) * 128 + wn + 4);
        *(float4*)&sWr[wk][wn]     = *(const float4*)(Wr + (size_t)(k0 + wk) * 128 + wn);
        *(float4*)&sWr[wk][wn + 4] = *(const float4*)(Wr + (size_t)(k0 + wk) * 128 + wn + 4);
        __syncthreads();

#pragma unroll
        for (int kk = 0; kk < 16; kk++) {
            unsigned long long wl[4], wr_[4];
            const unsigned long long* pl = (const unsigned long long*)&sWl[kk][tx * 8];
            const unsigned long long* pr = (const unsigned long long*)&sWr[kk][tx * 8];
#pragma unroll
            for (int j = 0; j < 4; j++) { wl[j] = pl[j]; wr_[j] = pr[j]; }
            float4 a1q = *(const float4*)&sA1[kk][ty * 4];
            float4 a2q = *(const float4*)&sA2[kk][ty * 4];
            float a1s[4] = {a1q.x, a1q.y, a1q.z, a1q.w};
            float a2s[4] = {a2q.x, a2q.y, a2q.z, a2q.w};
#pragma unroll
            for (int i = 0; i < 4; i++) {
                unsigned int a1u = __float_as_uint(a1s[i]);
                unsigned int a2u = __float_as_uint(a2s[i]);
                unsigned long long a1p, a2p;
                asm("mov.b64 %0, {%1, %1};" : "=l"(a1p) : "r"(a1u));
                asm("mov.b64 %0, {%1, %1};" : "=l"(a2p) : "r"(a2u));
#pragma unroll
                for (int j = 0; j < 4; j++) {
                    asm("fma.rn.f32x2 %0, %1, %2, %0;" : "+l"(acc[i][j]) : "l"(a1p), "l"(wl[j]));
                    asm("fma.rn.f32x2 %0, %1, %2, %0;" : "+l"(acc[i][j]) : "l"(a2p), "l"(wr_[j]));
                }
            }
        }
        __syncthreads();
    }

#pragma unroll
    for (int i = 0; i < 4; i++) {
        int row = m0 + ty * 4 + i;
        if (row >= NN) continue;
#pragma unroll
        for (int j = 0; j < 4; j++) {
            unsigned int lo, hi;
            asm("mov.b64 {%0, %1}, %2;" : "=r"(lo), "=r"(hi) : "l"(acc[i][j]));
            float v0 = __uint_as_float(lo) + bias[tx * 8 + j * 2];
            float v1 = __uint_as_float(hi) + bias[tx * 8 + j * 2 + 1];
            v0 = (v0 > 0.f) ? v0 : NEG * v0;
            v1 = (v1 > 0.f) ? v1 : NEG * v1;
            float2 o = make_float2(v0, v1);
            *(float2*)(Out + (size_t)row * HD + tx * 8 + j * 2) = o;
        }
    }
}

// ---------------- decoder GEMM (Nout=40) + fused log_softmax ----------------
// block: 32 rows x (8 thread-groups of 5 cols) = 256 threads
__global__ __launch_bounds__(256) void k_dec(
    int a2_id, const float* __restrict__ Wl, const float* __restrict__ Wr,
    const float* __restrict__ bias, float* __restrict__ out)
{
    __shared__ float sA1[32][128];
    __shared__ float sA2[32][128];
    __shared__ float sWl[32][40];
    __shared__ float sWr[32][40];

    const float* A1 = g_agg;
    const float* A2 = dev_buf(a2_id);
    int m0 = blockIdx.x * 32;
    int tid = (int)threadIdx.x;

    // stage A tiles (32 rows x 128)
    for (int i = tid; i < 32 * 32; i += 256) {
        int r = i >> 5;
        int c = (i & 31) * 4;
        int gr = m0 + r; if (gr >= NN) gr = NN - 1;
        *(float4*)&sA1[r][c] = *(const float4*)(A1 + (size_t)gr * HD + c);
        *(float4*)&sA2[r][c] = *(const float4*)(A2 + (size_t)gr * HD + c);
    }

    int r  = tid >> 3;   // 0..31
    int cg = tid & 7;    // cols cg*5..cg*5+4
    float acc[5];
#pragma unroll
    for (int j = 0; j < 5; j++) acc[j] = bias[cg * 5 + j];

    for (int k0 = 0; k0 < 128; k0 += 32) {
        __syncthreads();   // protects sW reuse; first pass also fences A staging
        for (int i = tid; i < 32 * 40; i += 256) {
            int k = i / 40, n = i % 40;
            sWl[k][n] = Wl[(size_t)(k0 + k) * 40 + n];
            sWr[k][n] = Wr[(size_t)(k0 + k) * 40 + n];
        }
        __syncthreads();
#pragma unroll
        for (int kk = 0; kk < 32; kk++) {
            float a1 = sA1[r][k0 + kk];
            float a2 = sA2[r][k0 + kk];
#pragma unroll
            for (int j = 0; j < 5; j++)
                acc[j] += a1 * sWl[kk][cg * 5 + j] + a2 * sWr[kk][cg * 5 + j];
        }
    }

    // log_softmax across the 8-thread group (40 cols)
    float m = acc[0];
#pragma unroll
    for (int j = 1; j < 5; j++) m = fmaxf(m, acc[j]);
#pragma unroll
    for (int off = 4; off >= 1; off >>= 1)
        m = fmaxf(m, __shfl_xor_sync(0xffffffffu, m, off, 8));
    float s = 0.f;
#pragma unroll
    for (int j = 0; j < 5; j++) s += __expf(acc[j] - m);
#pragma unroll
    for (int off = 4; off >= 1; off >>= 1)
        s += __shfl_xor_sync(0xffffffffu, s, off, 8);
    float lse = m + logf(s);

    int row = m0 + r;
    if (row < NN) {
#pragma unroll
        for (int j = 0; j < 5; j++)
            out[(size_t)row * CC + cg * 5 + j] = acc[j] - lse;
    }
}

// ---------------- host ----------------
extern "C" void kernel_launch(void* const* d_in, const int* in_sizes, int n_in,
                              void* d_out, int out_size) {
    (void)in_sizes; (void)n_in; (void)out_size;
    const float* x      = (const float*)d_in[0];
    const int*   ei     = (const int*)d_in[1];
    const int*   src    = ei;
    const int*   dst    = ei + EE;
    const float* enc_Wl = (const float*)d_in[2];
    const float* enc_Wr = (const float*)d_in[3];
    const float* enc_b  = (const float*)d_in[4];
    const float* lay_Wl = (const float*)d_in[5];
    const float* lay_Wr = (const float*)d_in[6];
    const float* lay_b  = (const float*)d_in[7];
    const float* dec_Wl = (const float*)d_in[8];
    const float* dec_Wr = (const float*)d_in[9];
    const float* dec_b  = (const float*)d_in[10];
    float* out = (float*)d_out;

    // CSR build
    k_zero_cnt<<<(NN + 255) / 256, 256>>>();
    k_deg<<<(EE + 255) / 256, 256>>>(dst);
    k_scan<<<1, 1024>>>();
    k_prep<<<(NN + 255) / 256, 256>>>();
    k_fill<<<(EE + 255) / 256, 256>>>(src, dst);

    int aggBlocks  = (NN + 7) / 8;      // 8 warps / block
    int gemmBlocks = (NN + 63) / 64;

    // encoder: h0(bufA) = lrelu(mean(x)@Wl + x@Wr + b)
    k_agg<<<aggBlocks, 256>>>(x, -1);
    k_gemm128<<<gemmBlocks, 256>>>(x, -1, enc_Wl, enc_Wr, enc_b, 0);
    // layer 0: bufB
    k_agg<<<aggBlocks, 256>>>(nullptr, 0);
    k_gemm128<<<gemmBlocks, 256>>>(nullptr, 0, lay_Wl, lay_Wr, lay_b, 1);
    // layer 1: bufA
    k_agg<<<aggBlocks, 256>>>(nullptr, 1);
    k_gemm128<<<gemmBlocks, 256>>>(nullptr, 1, lay_Wl + HD * HD, lay_Wr + HD * HD, lay_b + HD, 0);
    // decoder + log_softmax
    k_agg<<<aggBlocks, 256>>>(nullptr, 0);
    k_dec<<<(NN + 31) / 32, 256>>>(0, dec_Wl, dec_Wr, dec_b, out);
}

// round 8
// speedup vs baseline: 2.4999x; 2.4999x over previous
#include <cuda_runtime.h>
#include <cstdint>

#define NN 50000
#define EE 600000
#define HD 128
#define CC 40
#define NEG 0.1f

// ---------------- scratch (static device globals; no allocation) ----------------
__device__ float g_bufA[(size_t)NN * HD];
__device__ float g_bufB[(size_t)NN * HD];
__device__ float g_agg[(size_t)NN * HD];
__device__ float g_inv[NN];
__device__ int   g_cnt[NN];
__device__ int   g_rowptr[NN + 1];
__device__ int   g_rawscan[NN];
__device__ int   g_bsum[128];
__device__ int   g_boff[128];
__device__ int   g_fill[NN];
__device__ int   g_col[EE];
// pre-transposed + split-bf16 weights: W^T stored [N][K] row-major (K=128 contiguous)
__device__ unsigned short g_wth[108544];
__device__ unsigned short g_wtl[108544];

#define WOFF_ENCL 0
#define WOFF_ENCR 16384
#define WOFF_L0L  32768
#define WOFF_L0R  49152
#define WOFF_L1L  65536
#define WOFF_L1R  81920
#define WOFF_DECL 98304
#define WOFF_DECR 103424

__device__ __forceinline__ float* dev_buf(int id) {
    return (id == 0) ? g_bufA : g_bufB;
}

// ---------------- CSR build ----------------
__global__ void k_zero_cnt() {
    int i = blockIdx.x * blockDim.x + threadIdx.x;
    if (i < NN) g_cnt[i] = 0;
}

__global__ void k_deg(const int* __restrict__ dst) {
    int e = blockIdx.x * blockDim.x + threadIdx.x;
    if (e < EE) atomicAdd(&g_cnt[dst[e]], 1);
}

// per-block inclusive scan (512/block) -> g_rawscan, block totals -> g_bsum
__global__ void k_scan1() {
    __shared__ int s[512];
    int i = blockIdx.x * 512 + threadIdx.x;
    int v = (i < NN) ? g_cnt[i] : 0;
    s[threadIdx.x] = v;
    __syncthreads();
    for (int off = 1; off < 512; off <<= 1) {
        int t = (threadIdx.x >= (unsigned)off) ? s[threadIdx.x - off] : 0;
        __syncthreads();
        s[threadIdx.x] += t;
        __syncthreads();
    }
    if (i < NN) g_rawscan[i] = s[threadIdx.x];
    if (threadIdx.x == 511) g_bsum[blockIdx.x] = s[511];
}

// exclusive scan of block sums (single 128-thread block)
__global__ void k_scan2() {
    __shared__ int s[128];
    int t = threadIdx.x;
    int nb = (NN + 511) / 512;
    int v = (t < nb) ? g_bsum[t] : 0;
    s[t] = v;
    __syncthreads();
    for (int off = 1; off < 128; off <<= 1) {
        int u = (t >= off) ? s[t - off] : 0;
        __syncthreads();
        s[t] += u;
        __syncthreads();
    }
    if (t < nb) g_boff[t] = (t == 0) ? 0 : s[t - 1];
}

__global__ void k_prep() {
    int i = blockIdx.x * blockDim.x + threadIdx.x;
    if (i < NN) {
        int c = g_cnt[i];
        int end = g_rawscan[i] + g_boff[i >> 9];
        g_rowptr[i + 1] = end;
        g_fill[i] = end - c;
        g_inv[i] = 1.0f / (float)(c > 0 ? c : 1);
        if (i == 0) g_rowptr[0] = 0;
    }
}

__global__ void k_fill(const int* __restrict__ src, const int* __restrict__ dst) {
    int e = blockIdx.x * blockDim.x + threadIdx.x;
    if (e < EE) {
        int pos = atomicAdd(&g_fill[dst[e]], 1);
        g_col[pos] = src[e];
    }
}

// ---------------- mean aggregation: one warp per node, float4 lanes ----------------
__global__ void k_agg(const float* __restrict__ ext, int in_id) {
    int warp = (blockIdx.x * blockDim.x + threadIdx.x) >> 5;
    if (warp >= NN) return;
    int lane = threadIdx.x & 31;
    const float* in = (in_id < 0) ? ext : dev_buf(in_id);
    int beg = g_rowptr[warp];
    int end = g_rowptr[warp + 1];
    float4 acc = make_float4(0.f, 0.f, 0.f, 0.f);
    for (int e = beg; e < end; e++) {
        int srcn = g_col[e];
        float4 v = *(const float4*)(in + (size_t)srcn * HD + lane * 4);
        acc.x += v.x; acc.y += v.y; acc.z += v.z; acc.w += v.w;
    }
    float iv = g_inv[warp];
    acc.x *= iv; acc.y *= iv; acc.z *= iv; acc.w *= iv;
    *(float4*)(g_agg + (size_t)warp * HD + lane * 4) = acc;
}

// ---------------- weight prep: W^T, split bf16 hi/lo ----------------
__global__ void k_wprep(const float* __restrict__ eWl, const float* __restrict__ eWr,
                        const float* __restrict__ lWl, const float* __restrict__ lWr,
                        const float* __restrict__ dWl, const float* __restrict__ dWr) {
    int idx = blockIdx.x * blockDim.x + threadIdx.x;
    if (idx >= 108544) return;
    const float* src;
    int N, e, off;
    if (idx < 98304) {
        int m = idx >> 14; e = idx & 16383; N = 128; off = m << 14;
        switch (m) {
            case 0: src = eWl; break;
            case 1: src = eWr; break;
            case 2: src = lWl; break;
            case 3: src = lWr; break;
            case 4: src = lWl + 16384; break;
            default: src = lWr + 16384; break;
        }
    } else {
        int t = idx - 98304;
        int m = t / 5120; e = t % 5120; N = 40;
        off = 98304 + m * 5120;
        src = m ? dWr : dWl;
    }
    int n = e >> 7;
    int k = e & 127;
    float v = src[(size_t)k * N + n];
    unsigned hp;
    asm("cvt.rn.bf16x2.f32 %0, %1, %2;" : "=r"(hp) : "f"(v), "f"(v));
    unsigned hb = hp & 0xffffu;
    float hf = __uint_as_float(hb << 16);
    float lv = v - hf;
    unsigned lp;
    asm("cvt.rn.bf16x2.f32 %0, %1, %2;" : "=r"(lp) : "f"(lv), "f"(lv));
    g_wth[off + e] = (unsigned short)hb;
    g_wtl[off + e] = (unsigned short)(lp & 0xffffu);
}

// ---------------- mma.sync helpers ----------------
#define LDSM4(r, addr) \
    asm volatile("ldmatrix.sync.aligned.m8n8.x4.shared.b16 {%0,%1,%2,%3}, [%4];" \
        : "=r"((r)[0]), "=r"((r)[1]), "=r"((r)[2]), "=r"((r)[3]) : "r"(addr))

#define LDSM2(r, addr) \
    asm volatile("ldmatrix.sync.aligned.m8n8.x2.shared.b16 {%0,%1}, [%2];" \
        : "=r"((r)[0]), "=r"((r)[1]) : "r"(addr))

#define MMA16816(d, a, b) \
    asm volatile("mma.sync.aligned.m16n8k16.row.col.f32.bf16.bf16.f32 " \
        "{%0,%1,%2,%3}, {%4,%5,%6,%7}, {%8,%9}, {%0,%1,%2,%3};" \
        : "+f"((d)[0]), "+f"((d)[1]), "+f"((d)[2]), "+f"((d)[3]) \
        : "r"((a)[0]), "r"((a)[1]), "r"((a)[2]), "r"((a)[3]), "r"((b)[0]), "r"((b)[1]))

// swizzled byte offset inside a [rows][128 bf16] plane (256B rows, 16B-chunk XOR)
__device__ __forceinline__ unsigned sw_off(int r, unsigned cbyte) {
    return (unsigned)r * 256u + ((((cbyte >> 4) ^ (unsigned)(r & 7)) & 15u) << 4) + (cbyte & 15u);
}

// stage 128x128 fp32 tile -> split bf16 hi/lo planes (swizzled)
__device__ __forceinline__ void stage_A_sw(char* smhi, char* smlo,
                                           const float* __restrict__ src, int m0, int tid) {
    for (int t = tid; t < 4096; t += 256) {
        int r = t >> 5;
        int c4 = (t & 31) << 2;
        int gr = m0 + r; if (gr > NN - 1) gr = NN - 1;
        float4 v = *(const float4*)(src + (size_t)gr * HD + c4);
        unsigned h01, h23, l01, l23;
        asm("cvt.rn.bf16x2.f32 %0, %1, %2;" : "=r"(h01) : "f"(v.y), "f"(v.x));
        asm("cvt.rn.bf16x2.f32 %0, %1, %2;" : "=r"(h23) : "f"(v.w), "f"(v.z));
        float hx = __uint_as_float(h01 << 16), hy = __uint_as_float(h01 & 0xffff0000u);
        float hz = __uint_as_float(h23 << 16), hw = __uint_as_float(h23 & 0xffff0000u);
        asm("cvt.rn.bf16x2.f32 %0, %1, %2;" : "=r"(l01) : "f"(v.y - hy), "f"(v.x - hx));
        asm("cvt.rn.bf16x2.f32 %0, %1, %2;" : "=r"(l23) : "f"(v.w - hw), "f"(v.z - hz));
        unsigned off = sw_off(r, (unsigned)(c4 * 2));
        *(unsigned long long*)(smhi + off) = (unsigned long long)h01 | ((unsigned long long)h23 << 32);
        *(unsigned long long*)(smlo + off) = (unsigned long long)l01 | ((unsigned long long)l23 << 32);
    }
}

// stage W^T [nrows][128] bf16 hi/lo planes (swizzled)
__device__ __forceinline__ void stage_B_sw(char* smhi, char* smlo, int woff, int nrows, int tid) {
    int total = nrows * 32;
    for (int t = tid; t < total; t += 256) {
        int r = t >> 5;
        int c4 = (t & 31) << 2;
        unsigned long long vh = *(const unsigned long long*)(g_wth + woff + r * 128 + c4);
        unsigned long long vl = *(const unsigned long long*)(g_wtl + woff + r * 128 + c4);
        unsigned off = sw_off(r, (unsigned)(c4 * 2));
        *(unsigned long long*)(smhi + off) = vh;
        *(unsigned long long*)(smlo + off) = vl;
    }
}

// ---------------- mma GEMM: out = lrelu(agg@Wl + x@Wr + b), Nout=128 ----------------
// smem: A_hi 0, A_lo 32768, B_hi 65536, B_lo 98304  (total 131072)
__global__ __launch_bounds__(256, 1) void k_gemm_mma(
    const float* __restrict__ a2ext, int a2_id, int wl_off, int wr_off,
    const float* __restrict__ bias, int out_id)
{
    extern __shared__ char sm[];
    char* Ahi = sm;
    char* Alo = sm + 32768;
    char* Bhi = sm + 65536;
    char* Blo = sm + 98304;
    unsigned sAhi = (unsigned)__cvta_generic_to_shared(Ahi);
    unsigned sAlo = (unsigned)__cvta_generic_to_shared(Alo);
    unsigned sBhi = (unsigned)__cvta_generic_to_shared(Bhi);
    unsigned sBlo = (unsigned)__cvta_generic_to_shared(Blo);

    int tid = (int)threadIdx.x;
    int lane = tid & 31, wid = tid >> 5;
    int mwarp = wid & 3, nwarp = wid >> 2;
    int m0 = blockIdx.x * 128;
    const float* a2 = (a2_id < 0) ? a2ext : dev_buf(a2_id);

    float acc[2][8][4];
#pragma unroll
    for (int i = 0; i < 2; i++)
#pragma unroll
        for (int j = 0; j < 8; j++)
#pragma unroll
            for (int q = 0; q < 4; q++) acc[i][j][q] = 0.f;

    int arow0 = mwarp * 32 + (lane & 7) + ((lane >> 3) & 1) * 8;
    unsigned akoff = (unsigned)((lane >> 4) << 4);   // +16B for k+8 half
    int nrow0 = nwarp * 64 + (lane & 7);
    unsigned bkoff = (unsigned)(((lane >> 3) & 1) << 4);

    for (int ph = 0; ph < 2; ph++) {
        if (ph) __syncthreads();
        stage_A_sw(Ahi, Alo, ph ? a2 : g_agg, m0, tid);
        stage_B_sw(Bhi, Blo, ph ? wr_off : wl_off, 128, tid);
        __syncthreads();

        for (int k0 = 0; k0 < 128; k0 += 16) {
            unsigned ah[2][4], al[2][4], bh[8][2], bl[8][2];
            unsigned acb = (unsigned)(2 * k0) + akoff;
#pragma unroll
            for (int i = 0; i < 2; i++) {
                int r = arow0 + i * 16;
                unsigned off = sw_off(r, acb);
                LDSM4(ah[i], sAhi + off);
                LDSM4(al[i], sAlo + off);
            }
            unsigned bcb = (unsigned)(2 * k0) + bkoff;
#pragma unroll
            for (int j = 0; j < 8; j++) {
                int n = nrow0 + j * 8;
                unsigned off = sw_off(n, bcb);
                LDSM2(bh[j], sBhi + off);
                LDSM2(bl[j], sBlo + off);
            }
#pragma unroll
            for (int i = 0; i < 2; i++)
#pragma unroll
                for (int j = 0; j < 8; j++) {
                    MMA16816(acc[i][j], ah[i], bh[j]);
                    MMA16816(acc[i][j], ah[i], bl[j]);
                    MMA16816(acc[i][j], al[i], bh[j]);
                }
        }
    }

    // epilogue: bias + leaky relu, float2 stores
    float* Out = dev_buf(out_id);
    int r0 = mwarp * 32 + (lane >> 2);
    int cb0 = nwarp * 64 + (lane & 3) * 2;
#pragma unroll
    for (int i = 0; i < 2; i++) {
        int rowA = m0 + r0 + i * 16;
        int rowB = rowA + 8;
#pragma unroll
        for (int j = 0; j < 8; j++) {
            int col = cb0 + j * 8;
            float b0 = bias[col], b1 = bias[col + 1];
            float v0 = acc[i][j][0] + b0, v1 = acc[i][j][1] + b1;
            float v2 = acc[i][j][2] + b0, v3 = acc[i][j][3] + b1;
            v0 = (v0 > 0.f) ? v0 : NEG * v0;
            v1 = (v1 > 0.f) ? v1 : NEG * v1;
            v2 = (v2 > 0.f) ? v2 : NEG * v2;
            v3 = (v3 > 0.f) ? v3 : NEG * v3;
            if (rowA < NN) *(float2*)(Out + (size_t)rowA * HD + col) = make_float2(v0, v1);
            if (rowB < NN) *(float2*)(Out + (size_t)rowB * HD + col) = make_float2(v2, v3);
        }
    }
}

// ---------------- mma decoder (Nout=40) + fused log_softmax ----------------
// smem: A_hi 0, A_lo 32768, B_hi 65536, B_lo 75776 (total 86016); softmax scratch reuses B
__global__ __launch_bounds__(256, 1) void k_dec_mma(
    int a2_id, int wl_off, int wr_off,
    const float* __restrict__ bias, float* __restrict__ out)
{
    extern __shared__ char sm[];
    char* Ahi = sm;
    char* Alo = sm + 32768;
    char* Bhi = sm + 65536;
    char* Blo = sm + 75776;
    unsigned sAhi = (unsigned)__cvta_generic_to_shared(Ahi);
    unsigned sAlo = (unsigned)__cvta_generic_to_shared(Alo);
    unsigned sBhi = (unsigned)__cvta_generic_to_shared(Bhi);
    unsigned sBlo = (unsigned)__cvta_generic_to_shared(Blo);

    int tid = (int)threadIdx.x;
    int lane = tid & 31, wid = tid >> 5;
    int m0 = blockIdx.x * 128;
    const float* a2 = dev_buf(a2_id);

    float acc[5][4];
#pragma unroll
    for (int j = 0; j < 5; j++)
#pragma unroll
        for (int q = 0; q < 4; q++) acc[j][q] = 0.f;

    int arow0 = wid * 16 + (lane & 7) + ((lane >> 3) & 1) * 8;
    unsigned akoff = (unsigned)((lane >> 4) << 4);
    int nrow0 = (lane & 7);
    unsigned bkoff = (unsigned)(((lane >> 3) & 1) << 4);

    for (int ph = 0; ph < 2; ph++) {
        if (ph) __syncthreads();
        stage_A_sw(Ahi, Alo, ph ? a2 : g_agg, m0, tid);
        stage_B_sw(Bhi, Blo, ph ? wr_off : wl_off, 40, tid);
        __syncthreads();

        for (int k0 = 0; k0 < 128; k0 += 16) {
            unsigned ah[4], al[4], bh[5][2], bl[5][2];
            unsigned acb = (unsigned)(2 * k0) + akoff;
            unsigned aoff = sw_off(arow0, acb);
            LDSM4(ah, sAhi + aoff);
            LDSM4(al, sAlo + aoff);
            unsigned bcb = (unsigned)(2 * k0) + bkoff;
#pragma unroll
            for (int j = 0; j < 5; j++) {
                int n = nrow0 + j * 8;
                unsigned off = sw_off(n, bcb);
                LDSM2(bh[j], sBhi + off);
                LDSM2(bl[j], sBlo + off);
            }
#pragma unroll
            for (int j = 0; j < 5; j++) {
                MMA16816(acc[j], ah, bh[j]);
                MMA16816(acc[j], ah, bl[j]);
                MMA16816(acc[j], al, bh[j]);
            }
        }
    }
    __syncthreads();   // all B reads done; reuse B region as scratch

    float* scr = (float*)(sm + 65536);
    float* w = scr + wid * 640;          // 16 rows x 40
    int r0 = lane >> 2, c0 = (lane & 3) * 2;
#pragma unroll
    for (int j = 0; j < 5; j++) {
        int col = j * 8 + c0;
        w[r0 * 40 + col]       = acc[j][0];
        w[r0 * 40 + col + 1]   = acc[j][1];
        w[(r0 + 8) * 40 + col]     = acc[j][2];
        w[(r0 + 8) * 40 + col + 1] = acc[j][3];
    }
    __syncwarp();

    if (lane < 16) {
        float a[40];
#pragma unroll
        for (int c = 0; c < 40; c++) a[c] = w[lane * 40 + c] + bias[c];
        float m = a[0];
#pragma unroll
        for (int c = 1; c < 40; c++) m = fmaxf(m, a[c]);
        float s = 0.f;
#pragma unroll
        for (int c = 0; c < 40; c++) s += __expf(a[c] - m);
        float lse = m + logf(s);
        int row = m0 + wid * 16 + lane;
        if (row < NN) {
#pragma unroll
            for (int j = 0; j < 10; j++) {
                float4 o;
                o.x = a[j * 4 + 0] - lse;
                o.y = a[j * 4 + 1] - lse;
                o.z = a[j * 4 + 2] - lse;
                o.w = a[j * 4 + 3] - lse;
                *(float4*)(out + (size_t)row * CC + j * 4) = o;
            }
        }
    }
}

// ---------------- host ----------------
#define GEMM_SMEM 131072
#define DEC_SMEM  86016

extern "C" void kernel_launch(void* const* d_in, const int* in_sizes, int n_in,
                              void* d_out, int out_size) {
    (void)in_sizes; (void)n_in; (void)out_size;
    const float* x      = (const float*)d_in[0];
    const int*   ei     = (const int*)d_in[1];
    const int*   src    = ei;
    const int*   dst    = ei + EE;
    const float* enc_Wl = (const float*)d_in[2];
    const float* enc_Wr = (const float*)d_in[3];
    const float* enc_b  = (const float*)d_in[4];
    const float* lay_Wl = (const float*)d_in[5];
    const float* lay_Wr = (const float*)d_in[6];
    const float* lay_b  = (const float*)d_in[7];
    const float* dec_Wl = (const float*)d_in[8];
    const float* dec_Wr = (const float*)d_in[9];
    const float* dec_b  = (const float*)d_in[10];
    float* out = (float*)d_out;

    cudaFuncSetAttribute(k_gemm_mma, cudaFuncAttributeMaxDynamicSharedMemorySize, GEMM_SMEM);
    cudaFuncSetAttribute(k_dec_mma,  cudaFuncAttributeMaxDynamicSharedMemorySize, DEC_SMEM);

    // CSR build
    k_zero_cnt<<<(NN + 255) / 256, 256>>>();
    k_deg<<<(EE + 255) / 256, 256>>>(dst);
    k_scan1<<<(NN + 511) / 512, 512>>>();
    k_scan2<<<1, 128>>>();
    k_prep<<<(NN + 255) / 256, 256>>>();
    k_fill<<<(EE + 255) / 256, 256>>>(src, dst);

    // weight prep (transpose + split bf16)
    k_wprep<<<(108544 + 255) / 256, 256>>>(enc_Wl, enc_Wr, lay_Wl, lay_Wr, dec_Wl, dec_Wr);

    int aggBlocks  = (NN + 7) / 8;       // 8 warps / block
    int gemmBlocks = (NN + 127) / 128;   // 391

    // encoder: h0(bufA) = lrelu(mean(x)@Wl + x@Wr + b)
    k_agg<<<aggBlocks, 256>>>(x, -1);
    k_gemm_mma<<<gemmBlocks, 256, GEMM_SMEM>>>(x, -1, WOFF_ENCL, WOFF_ENCR, enc_b, 0);
    // layer 0: bufB
    k_agg<<<aggBlocks, 256>>>(nullptr, 0);
    k_gemm_mma<<<gemmBlocks, 256, GEMM_SMEM>>>(nullptr, 0, WOFF_L0L, WOFF_L0R, lay_b, 1);
    // layer 1: bufA
    k_agg<<<aggBlocks, 256>>>(nullptr, 1);
    k_gemm_mma<<<gemmBlocks, 256, GEMM_SMEM>>>(nullptr, 1, WOFF_L1L, WOFF_L1R, lay_b + HD, 0);
    // decoder + log_softmax
    k_agg<<<aggBlocks, 256>>>(nullptr, 0);
    k_dec_mma<<<gemmBlocks, 256, DEC_SMEM>>>(0, WOFF_DECL, WOFF_DECR, dec_b, out);
}

// round 12
// speedup vs baseline: 2.5005x; 1.0002x over previous
#include <cuda_runtime.h>
#include <cstdint>

#define NN 50000
#define EE 600000
#define HD 128
#define CC 40
#define NEG 0.1f
#define NTILES ((NN + 127) / 128)

// ---------------- scratch (static device globals; no allocation) ----------------
__device__ float g_bufA[(size_t)NN * HD];
__device__ float g_bufB[(size_t)NN * HD];
__device__ float g_agg[(size_t)NN * HD];
__device__ float g_inv[NN];
__device__ int   g_cnt[NN];
__device__ int   g_rowptr[NN + 1];
__device__ int   g_rawscan[NN];
__device__ int   g_bsum[128];
__device__ int   g_boff[128];
__device__ int   g_fill[NN];
__device__ int   g_col[EE];
// pre-transposed + split-bf16 weights: W^T stored [N][K] row-major (K=128 contiguous)
__device__ unsigned short g_wth[108544];
__device__ unsigned short g_wtl[108544];

#define WOFF_ENCL 0
#define WOFF_ENCR 16384
#define WOFF_L0L  32768
#define WOFF_L0R  49152
#define WOFF_L1L  65536
#define WOFF_L1R  81920
#define WOFF_DECL 98304
#define WOFF_DECR 103424

__device__ __forceinline__ float* dev_buf(int id) {
    return (id == 0) ? g_bufA : g_bufB;
}

// ---------------- CSR build ----------------
__global__ void k_zero_cnt() {
    int i = blockIdx.x * blockDim.x + threadIdx.x;
    if (i < NN) g_cnt[i] = 0;
}

__global__ void k_deg(const int* __restrict__ dst) {
    int e = blockIdx.x * blockDim.x + threadIdx.x;
    if (e < EE) atomicAdd(&g_cnt[dst[e]], 1);
}

// per-block inclusive scan (512/block) -> g_rawscan, block totals -> g_bsum
__global__ void k_scan1() {
    __shared__ int s[512];
    int i = blockIdx.x * 512 + threadIdx.x;
    int v = (i < NN) ? g_cnt[i] : 0;
    s[threadIdx.x] = v;
    __syncthreads();
    for (int off = 1; off < 512; off <<= 1) {
        int t = (threadIdx.x >= (unsigned)off) ? s[threadIdx.x - off] : 0;
        __syncthreads();
        s[threadIdx.x] += t;
        __syncthreads();
    }
    if (i < NN) g_rawscan[i] = s[threadIdx.x];
    if (threadIdx.x == 511) g_bsum[blockIdx.x] = s[511];
}

// exclusive scan of block sums (single 128-thread block)
__global__ void k_scan2() {
    __shared__ int s[128];
    int t = threadIdx.x;
    int nb = (NN + 511) / 512;
    int v = (t < nb) ? g_bsum[t] : 0;
    s[t] = v;
    __syncthreads();
    for (int off = 1; off < 128; off <<= 1) {
        int u = (t >= off) ? s[t - off] : 0;
        __syncthreads();
        s[t] += u;
        __syncthreads();
    }
    if (t < nb) g_boff[t] = (t == 0) ? 0 : s[t - 1];
}

__global__ void k_prep() {
    int i = blockIdx.x * blockDim.x + threadIdx.x;
    if (i < NN) {
        int c = g_cnt[i];
        int end = g_rawscan[i] + g_boff[i >> 9];
        g_rowptr[i + 1] = end;
        g_fill[i] = end - c;
        g_inv[i] = 1.0f / (float)(c > 0 ? c : 1);
        if (i == 0) g_rowptr[0] = 0;
    }
}

__global__ void k_fill(const int* __restrict__ src, const int* __restrict__ dst) {
    int e = blockIdx.x * blockDim.x + threadIdx.x;
    if (e < EE) {
        int pos = atomicAdd(&g_fill[dst[e]], 1);
        g_col[pos] = src[e];
    }
}

// ---------------- mean aggregation: one warp per node, float4 lanes ----------------
__global__ void k_agg(const float* __restrict__ ext, int in_id) {
    int warp = (blockIdx.x * blockDim.x + threadIdx.x) >> 5;
    if (warp >= NN) return;
    int lane = threadIdx.x & 31;
    const float* in = (in_id < 0) ? ext : dev_buf(in_id);
    int beg = g_rowptr[warp];
    int end = g_rowptr[warp + 1];
    float4 acc = make_float4(0.f, 0.f, 0.f, 0.f);
    for (int e = beg; e < end; e++) {
        int srcn = g_col[e];
        float4 v = *(const float4*)(in + (size_t)srcn * HD + lane * 4);
        acc.x += v.x; acc.y += v.y; acc.z += v.z; acc.w += v.w;
    }
    float iv = g_inv[warp];
    acc.x *= iv; acc.y *= iv; acc.z *= iv; acc.w *= iv;
    *(float4*)(g_agg + (size_t)warp * HD + lane * 4) = acc;
}

// ---------------- weight prep: W^T, split bf16 hi/lo ----------------
__global__ void k_wprep(const float* __restrict__ eWl, const float* __restrict__ eWr,
                        const float* __restrict__ lWl, const float* __restrict__ lWr,
                        const float* __restrict__ dWl, const float* __restrict__ dWr) {
    int idx = blockIdx.x * blockDim.x + threadIdx.x;
    if (idx >= 108544) return;
    const float* src;
    int N, e, off;
    if (idx < 98304) {
        int m = idx >> 14; e = idx & 16383; N = 128; off = m << 14;
        switch (m) {
            case 0: src = eWl; break;
            case 1: src = eWr; break;
            case 2: src = lWl; break;
            case 3: src = lWr; break;
            case 4: src = lWl + 16384; break;
            default: src = lWr + 16384; break;
        }
    } else {
        int t = idx - 98304;
        int m = t / 5120; e = t % 5120; N = 40;
        off = 98304 + m * 5120;
        src = m ? dWr : dWl;
    }
    int n = e >> 7;
    int k = e & 127;
    float v = src[(size_t)k * N + n];
    unsigned hp;
    asm("cvt.rn.bf16x2.f32 %0, %1, %2;" : "=r"(hp) : "f"(v), "f"(v));
    unsigned hb = hp & 0xffffu;
    float hf = __uint_as_float(hb << 16);
    float lv = v - hf;
    unsigned lp;
    asm("cvt.rn.bf16x2.f32 %0, %1, %2;" : "=r"(lp) : "f"(lv), "f"(lv));
    g_wth[off + e] = (unsigned short)hb;
    g_wtl[off + e] = (unsigned short)(lp & 0xffffu);
}

// ---------------- mma.sync helpers ----------------
#define LDSM4(r, addr) \
    asm volatile("ldmatrix.sync.aligned.m8n8.x4.shared.b16 {%0,%1,%2,%3}, [%4];" \
        : "=r"((r)[0]), "=r"((r)[1]), "=r"((r)[2]), "=r"((r)[3]) : "r"(addr))

#define LDSM2(r, addr) \
    asm volatile("ldmatrix.sync.aligned.m8n8.x2.shared.b16 {%0,%1}, [%2];" \
        : "=r"((r)[0]), "=r"((r)[1]) : "r"(addr))

#define MMA16816(d, a, b) \
    asm volatile("mma.sync.aligned.m16n8k16.row.col.f32.bf16.bf16.f32 " \
        "{%0,%1,%2,%3}, {%4,%5,%6,%7}, {%8,%9}, {%0,%1,%2,%3};" \
        : "+f"((d)[0]), "+f"((d)[1]), "+f"((d)[2]), "+f"((d)[3]) \
        : "r"((a)[0]), "r"((a)[1]), "r"((a)[2]), "r"((a)[3]), "r"((b)[0]), "r"((b)[1]))

// swizzled byte offset inside a [rows][128 bf16] plane (256B rows, 16B-chunk XOR)
__device__ __forceinline__ unsigned sw_off(int r, unsigned cbyte) {
    return (unsigned)r * 256u + ((((cbyte >> 4) ^ (unsigned)(r & 7)) & 15u) << 4) + (cbyte & 15u);
}

// stage 128x128 fp32 tile -> split bf16 hi/lo planes (swizzled)
__device__ __forceinline__ void stage_A_sw(char* smhi, char* smlo,
                                           const float* __restrict__ src, int m0, int tid) {
    for (int t = tid; t < 4096; t += 256) {
        int r = t >> 5;
        int c4 = (t & 31) << 2;
        int gr = m0 + r; if (gr > NN - 1) gr = NN - 1;
        float4 v = *(const float4*)(src + (size_t)gr * HD + c4);
        unsigned h01, h23, l01, l23;
        asm("cvt.rn.bf16x2.f32 %0, %1, %2;" : "=r"(h01) : "f"(v.y), "f"(v.x));
        asm("cvt.rn.bf16x2.f32 %0, %1, %2;" : "=r"(h23) : "f"(v.w), "f"(v.z));
        float hx = __uint_as_float(h01 << 16), hy = __uint_as_float(h01 & 0xffff0000u);
        float hz = __uint_as_float(h23 << 16), hw = __uint_as_float(h23 & 0xffff0000u);
        asm("cvt.rn.bf16x2.f32 %0, %1, %2;" : "=r"(l01) : "f"(v.y - hy), "f"(v.x - hx));
        asm("cvt.rn.bf16x2.f32 %0, %1, %2;" : "=r"(l23) : "f"(v.w - hw), "f"(v.z - hz));
        unsigned off = sw_off(r, (unsigned)(c4 * 2));
        *(unsigned long long*)(smhi + off) = (unsigned long long)h01 | ((unsigned long long)h23 << 32);
        *(unsigned long long*)(smlo + off) = (unsigned long long)l01 | ((unsigned long long)l23 << 32);
    }
}

// ---------------- persistent mma GEMM: out = lrelu(agg@Wl + x@Wr + b), Nout=128 ----------------
// smem: A_hi 0, A_lo 32768, B planes 65536 + p*32768 (p: Wl_hi, Wl_lo, Wr_hi, Wr_lo) = 196608
__global__ __launch_bounds__(256, 1) void k_gemm_mma(
    const float* __restrict__ a2ext, int a2_id, int wl_off, int wr_off,
    const float* __restrict__ bias, int out_id)
{
    extern __shared__ char sm[];
    char* Ahi = sm;
    char* Alo = sm + 32768;
    unsigned sAhi = (unsigned)__cvta_generic_to_shared(Ahi);
    unsigned sAlo = (unsigned)__cvta_generic_to_shared(Alo);
    unsigned sB   = (unsigned)__cvta_generic_to_shared(sm + 65536);

    int tid = (int)threadIdx.x;
    int lane = tid & 31, wid = tid >> 5;
    int mwarp = wid & 3, nwarp = wid >> 2;
    const float* a2 = (a2_id < 0) ? a2ext : dev_buf(a2_id);
    float* Out = dev_buf(out_id);

    // stage all four weight planes ONCE
    for (int t = tid; t < 4 * 4096; t += 256) {
        int mtx = t >> 12;
        int e = t & 4095;
        int r = e >> 5, c4 = (e & 31) << 2;
        const unsigned short* wp = ((mtx & 1) ? g_wtl : g_wth) + ((mtx < 2) ? wl_off : wr_off);
        unsigned long long v = *(const unsigned long long*)(wp + r * 128 + c4);
        *(unsigned long long*)(sm + 65536 + mtx * 32768 + sw_off(r, (unsigned)(c4 * 2))) = v;
    }

    int arow0 = mwarp * 32 + (lane & 7) + ((lane >> 3) & 1) * 8;
    unsigned akoff = (unsigned)((lane >> 4) << 4);   // +16B for k+8 half
    int nrow0 = nwarp * 64 + (lane & 7);
    unsigned bkoff = (unsigned)(((lane >> 3) & 1) << 4);

    // hoist bias for this thread's 16 columns
    int r0 = mwarp * 32 + (lane >> 2);
    int cb0 = nwarp * 64 + (lane & 3) * 2;
    float bv0[8], bv1[8];
#pragma unroll
    for (int j = 0; j < 8; j++) { bv0[j] = bias[cb0 + j * 8]; bv1[j] = bias[cb0 + j * 8 + 1]; }

    for (int tile = (int)blockIdx.x; tile < NTILES; tile += (int)gridDim.x) {
        int m0 = tile * 128;

        float acc[2][8][4];
#pragma unroll
        for (int i = 0; i < 2; i++)
#pragma unroll
            for (int j = 0; j < 8; j++)
#pragma unroll
                for (int q = 0; q < 4; q++) acc[i][j][q] = 0.f;

#pragma unroll
        for (int ph = 0; ph < 2; ph++) {
            __syncthreads();   // previous tile's / phase's ldmatrix A reads done; B staged (first pass)
            stage_A_sw(Ahi, Alo, ph ? a2 : g_agg, m0, tid);
            __syncthreads();

            unsigned sBhi = sB + (ph ? 65536u : 0u);
            unsigned sBlo = sBhi + 32768u;

            for (int k0 = 0; k0 < 128; k0 += 16) {
                unsigned ah[2][4], al[2][4], bh[8][2], bl[8][2];
                unsigned acb = (unsigned)(2 * k0) + akoff;
#pragma unroll
                for (int i = 0; i < 2; i++) {
                    int r = arow0 + i * 16;
                    unsigned off = sw_off(r, acb);
                    LDSM4(ah[i], sAhi + off);
                    LDSM4(al[i], sAlo + off);
                }
                unsigned bcb = (unsigned)(2 * k0) + bkoff;
#pragma unroll
                for (int j = 0; j < 8; j++) {
                    int n = nrow0 + j * 8;
                    unsigned off = sw_off(n, bcb);
                    LDSM2(bh[j], sBhi + off);
                    LDSM2(bl[j], sBlo + off);
                }
#pragma unroll
                for (int i = 0; i < 2; i++)
#pragma unroll
                    for (int j = 0; j < 8; j++) {
                        MMA16816(acc[i][j], ah[i], bh[j]);
                        MMA16816(acc[i][j], ah[i], bl[j]);
                        MMA16816(acc[i][j], al[i], bh[j]);
                    }
            }
        }

        // epilogue: bias + leaky relu, float2 stores
#pragma unroll
        for (int i = 0; i < 2; i++) {
            int rowA = m0 + r0 + i * 16;
            int rowB = rowA + 8;
#pragma unroll
            for (int j = 0; j < 8; j++) {
                int col = cb0 + j * 8;
                float v0 = acc[i][j][0] + bv0[j], v1 = acc[i][j][1] + bv1[j];
                float v2 = acc[i][j][2] + bv0[j], v3 = acc[i][j][3] + bv1[j];
                v0 = (v0 > 0.f) ? v0 : NEG * v0;
                v1 = (v1 > 0.f) ? v1 : NEG * v1;
                v2 = (v2 > 0.f) ? v2 : NEG * v2;
                v3 = (v3 > 0.f) ? v3 : NEG * v3;
                if (rowA < NN) *(float2*)(Out + (size_t)rowA * HD + col) = make_float2(v0, v1);
                if (rowB < NN) *(float2*)(Out + (size_t)rowB * HD + col) = make_float2(v2, v3);
            }
        }
    }
}

// ---------------- persistent mma decoder (Nout=40) + fused log_softmax ----------------
// smem: A_hi 0, A_lo 32768, B planes 65536 + p*10240 (total 106496); softmax scratch reuses A
__global__ __launch_bounds__(256, 2) void k_dec_mma(
    int a2_id, int wl_off, int wr_off,
    const float* __restrict__ bias, float* __restrict__ out)
{
    extern __shared__ char sm[];
    char* Ahi = sm;
    char* Alo = sm + 32768;
    unsigned sAhi = (unsigned)__cvta_generic_to_shared(Ahi);
    unsigned sAlo = (unsigned)__cvta_generic_to_shared(Alo);
    unsigned sB   = (unsigned)__cvta_generic_to_shared(sm + 65536);

    int tid = (int)threadIdx.x;
    int lane = tid & 31, wid = tid >> 5;
    const float* a2 = dev_buf(a2_id);

    // stage all four decoder weight planes ONCE (40 rows each)
    for (int t = tid; t < 4 * 1280; t += 256) {
        int mtx = t / 1280;
        int e = t % 1280;
        int r = e >> 5, c4 = (e & 31) << 2;
        const unsigned short* wp = ((mtx & 1) ? g_wtl : g_wth) + ((mtx < 2) ? wl_off : wr_off);
        unsigned long long v = *(const unsigned long long*)(wp + r * 128 + c4);
        *(unsigned long long*)(sm + 65536 + mtx * 10240 + sw_off(r, (unsigned)(c4 * 2))) = v;
    }

    int arow0 = wid * 16 + (lane & 7) + ((lane >> 3) & 1) * 8;
    unsigned akoff = (unsigned)((lane >> 4) << 4);
    int nrow0 = (lane & 7);
    unsigned bkoff = (unsigned)(((lane >> 3) & 1) << 4);

    for (int tile = (int)blockIdx.x; tile < NTILES; tile += (int)gridDim.x) {
        int m0 = tile * 128;

        float acc[5][4];
#pragma unroll
        for (int j = 0; j < 5; j++)
#pragma unroll
            for (int q = 0; q < 4; q++) acc[j][q] = 0.f;

#pragma unroll
        for (int ph = 0; ph < 2; ph++) {
            __syncthreads();   // prior scratch reads / ldmatrix done; B staged (first pass)
            stage_A_sw(Ahi, Alo, ph ? a2 : g_agg, m0, tid);
            __syncthreads();

            unsigned sBhi = sB + (ph ? 20480u : 0u);
            unsigned sBlo = sBhi + 10240u;

            for (int k0 = 0; k0 < 128; k0 += 16) {
                unsigned ah[4], al[4], bh[5][2], bl[5][2];
                unsigned acb = (unsigned)(2 * k0) + akoff;
                unsigned aoff = sw_off(arow0, acb);
                LDSM4(ah, sAhi + aoff);
                LDSM4(al, sAlo + aoff);
                unsigned bcb = (unsigned)(2 * k0) + bkoff;
#pragma unroll
                for (int j = 0; j < 5; j++) {
                    int n = nrow0 + j * 8;
                    unsigned off = sw_off(n, bcb);
                    LDSM2(bh[j], sBhi + off);
                    LDSM2(bl[j], sBlo + off);
                }
#pragma unroll
                for (int j = 0; j < 5; j++) {
                    MMA16816(acc[j], ah, bh[j]);
                    MMA16816(acc[j], ah, bl[j]);
                    MMA16816(acc[j], al, bh[j]);
                }
            }
        }
        __syncthreads();   // all ldmatrix A reads done; reuse A region as scratch

        float* w = (float*)sm + wid * 640;   // 16 rows x 40
        int r0 = lane >> 2, c0 = (lane & 3) * 2;
#pragma unroll
        for (int j = 0; j < 5; j++) {
            int col = j * 8 + c0;
            w[r0 * 40 + col]       = acc[j][0];
            w[r0 * 40 + col + 1]   = acc[j][1];
            w[(r0 + 8) * 40 + col]     = acc[j][2];
            w[(r0 + 8) * 40 + col + 1] = acc[j][3];
        }
        __syncwarp();

        if (lane < 16) {
            float a[40];
#pragma unroll
            for (int c = 0; c < 40; c++) a[c] = w[lane * 40 + c] + bias[c];
            float m = a[0];
#pragma unroll
            for (int c = 1; c < 40; c++) m = fmaxf(m, a[c]);
            float s = 0.f;
#pragma unroll
            for (int c = 0; c < 40; c++) s += __expf(a[c] - m);
            float lse = m + logf(s);
            int row = m0 + wid * 16 + lane;
            if (row < NN) {
#pragma unroll
                for (int j = 0; j < 10; j++) {
                    float4 o;
                    o.x = a[j * 4 + 0] - lse;
                    o.y = a[j * 4 + 1] - lse;
                    o.z = a[j * 4 + 2] - lse;
                    o.w = a[j * 4 + 3] - lse;
                    *(float4*)(out + (size_t)row * CC + j * 4) = o;
                }
            }
        }
        __syncwarp();
    }
}

// ---------------- host ----------------
#define GEMM_SMEM 196608
#define DEC_SMEM  106496
#define NSM 152

extern "C" void kernel_launch(void* const* d_in, const int* in_sizes, int n_in,
                              void* d_out, int out_size) {
    (void)in_sizes; (void)n_in; (void)out_size;
    const float* x      = (const float*)d_in[0];
    const int*   ei     = (const int*)d_in[1];
    const int*   src    = ei;
    const int*   dst    = ei + EE;
    const float* enc_Wl = (const float*)d_in[2];
    const float* enc_Wr = (const float*)d_in[3];
    const float* enc_b  = (const float*)d_in[4];
    const float* lay_Wl = (const float*)d_in[5];
    const float* lay_Wr = (const float*)d_in[6];
    const float* lay_b  = (const float*)d_in[7];
    const float* dec_Wl = (const float*)d_in[8];
    const float* dec_Wr = (const float*)d_in[9];
    const float* dec_b  = (const float*)d_in[10];
    float* out = (float*)d_out;

    cudaFuncSetAttribute(k_gemm_mma, cudaFuncAttributeMaxDynamicSharedMemorySize, GEMM_SMEM);
    cudaFuncSetAttribute(k_dec_mma,  cudaFuncAttributeMaxDynamicSharedMemorySize, DEC_SMEM);

    // CSR build
    k_zero_cnt<<<(NN + 255) / 256, 256>>>();
    k_deg<<<(EE + 255) / 256, 256>>>(dst);
    k_scan1<<<(NN + 511) / 512, 512>>>();
    k_scan2<<<1, 128>>>();
    k_prep<<<(NN + 255) / 256, 256>>>();
    k_fill<<<(EE + 255) / 256, 256>>>(src, dst);

    // weight prep (transpose + split bf16)
    k_wprep<<<(108544 + 255) / 256, 256>>>(enc_Wl, enc_Wr, lay_Wl, lay_Wr, dec_Wl, dec_Wr);

    int aggBlocks = (NN + 7) / 8;       // 8 warps / block

    // encoder: h0(bufA) = lrelu(mean(x)@Wl + x@Wr + b)
    k_agg<<<aggBlocks, 256>>>(x, -1);
    k_gemm_mma<<<NSM, 256, GEMM_SMEM>>>(x, -1, WOFF_ENCL, WOFF_ENCR, enc_b, 0);
    // layer 0: bufB
    k_agg<<<aggBlocks, 256>>>(nullptr, 0);
    k_gemm_mma<<<NSM, 256, GEMM_SMEM>>>(nullptr, 0, WOFF_L0L, WOFF_L0R, lay_b, 1);
    // layer 1: bufA
    k_agg<<<aggBlocks, 256>>>(nullptr, 1);
    k_gemm_mma<<<NSM, 256, GEMM_SMEM>>>(nullptr, 1, WOFF_L1L, WOFF_L1R, lay_b + HD, 0);
    // decoder + log_softmax
    k_agg<<<aggBlocks, 256>>>(nullptr, 0);
    k_dec_mma<<<2 * NSM, 256, DEC_SMEM>>>(0, WOFF_DECL, WOFF_DECR, dec_b, out);
}